// round 1
// baseline (speedup 1.0000x reference)
#include <cuda_runtime.h>

// ComputeWindowSignature: depth-3 path signature over sliding windows.
// B=256, L=2048, C=6, WIN=64, STRIDE=32 -> 63 windows, 63 increments each.
// Output per (b,w): [s1 (6), 2*s2 (36), 6*s3 (216)] = 258 floats.
//
// Decomposition: Chen update for fixed leading index i is independent of other
// leading indices -> 6 threads per (b,w), each owns s1[i], S2[i,:], S3[i,:,:]
// where S2 = 2*s2, S3 = 6*s3 (absorbs the final output scaling):
//   coef_j = (d_i + 3*s1_i)*d_j + 3*S2[i][j]
//   S3[i][j][k] += coef_j * d_k            (36 FMA)
//   S2[i][j]    += (d_i + 2*s1_i) * d_j    (6 FMA)
//   s1_i        += d_i
// (updates use OLD s1/S2: coef and b2 are computed before S2/s1 are touched)

namespace {

constexpr int BATCH   = 256;
constexpr int LEN     = 2048;
constexpr int CH      = 6;
constexpr int NW      = 63;    // number of windows
constexpr int NSTEP   = 63;    // increments per window
constexpr int NDX     = 2047;  // increments per full row
constexpr int SROW    = 2113;  // odd padded row stride (2047 + 64 pad, then odd)
constexpr int THREADS = 384;   // 63 windows * 6 lanes = 378 active
constexpr int SMEM_BYTES = CH * SROW * (int)sizeof(float);

__global__ __launch_bounds__(THREADS, 2)
void sig_kernel(const float* __restrict__ path, float* __restrict__ out) {
    extern __shared__ float s_dx[];  // [CH][SROW], element l stored at l + (l>>5)

    const int b   = blockIdx.x;
    const int tid = threadIdx.x;
    const float* __restrict__ row = path + (long long)b * (LEN * CH);

    // Stage increments dx[l][c] = path[l+1][c] - path[l][c] into shared,
    // channel-major with per-32 padding. Global reads are fully coalesced.
    for (int idx = tid; idx < NDX * CH; idx += THREADS) {
        const int l = idx / CH;
        const int c = idx - l * CH;
        const float d = row[idx + CH] - row[idx];
        s_dx[c * SROW + l + (l >> 5)] = d;
    }
    __syncthreads();

    if (tid >= NW * CH) return;
    const int w = tid / CH;       // window index 0..62
    const int i = tid - w * CH;   // leading channel index 0..5

    float s1 = 0.0f;
    float S2[6];
    float S3[6][6];
#pragma unroll
    for (int j = 0; j < 6; ++j) {
        S2[j] = 0.0f;
#pragma unroll
        for (int k = 0; k < 6; ++k) S3[j][k] = 0.0f;
    }

    const float* __restrict__ rowi = s_dx + i * SROW;
    const int base = w * 33;  // padded offset of l = w*32

#pragma unroll 7
    for (int t = 0; t < NSTEP; ++t) {
        const int off = base + t + (t >> 5);  // = l + (l>>5), l = 32w + t
        float d[6];
        d[0] = s_dx[0 * SROW + off];
        d[1] = s_dx[1 * SROW + off];
        d[2] = s_dx[2 * SROW + off];
        d[3] = s_dx[3 * SROW + off];
        d[4] = s_dx[4 * SROW + off];
        d[5] = s_dx[5 * SROW + off];
        const float di = rowi[off];

        const float a  = fmaf(3.0f, s1, di);  // d_i + 3*s1 (old s1)
        const float b2 = fmaf(2.0f, s1, di);  // d_i + 2*s1 (old s1)

#pragma unroll
        for (int j = 0; j < 6; ++j) {
            const float coef = fmaf(3.0f, S2[j], a * d[j]);  // old S2
#pragma unroll
            for (int k = 0; k < 6; ++k)
                S3[j][k] = fmaf(coef, d[k], S3[j][k]);
        }
#pragma unroll
        for (int j = 0; j < 6; ++j) S2[j] = fmaf(b2, d[j], S2[j]);
        s1 += di;
    }

    // Output: sig[b][w][0:6]=s1, [6:42]=2*s2 (i*6+j), [42:258]=6*s3 (i*36+j*6+k)
    float* __restrict__ o = out + ((long long)b * NW + w) * 258;
    o[i] = s1;
#pragma unroll
    for (int j = 0; j < 6; ++j) o[6 + i * 6 + j] = S2[j];
#pragma unroll
    for (int j = 0; j < 6; ++j)
#pragma unroll
        for (int k = 0; k < 6; ++k) o[42 + i * 36 + j * 6 + k] = S3[j][k];
}

}  // namespace

extern "C" void kernel_launch(void* const* d_in, const int* in_sizes, int n_in,
                              void* d_out, int out_size) {
    const float* path = (const float*)d_in[0];
    float* out = (float*)d_out;
    // 50.7 KB dynamic smem > 48 KB default: opt in (host attr call, capture-safe).
    cudaFuncSetAttribute(sig_kernel, cudaFuncAttributeMaxDynamicSharedMemorySize,
                         SMEM_BYTES);
    sig_kernel<<<BATCH, THREADS, SMEM_BYTES>>>(path, out);
}

// round 2
// speedup vs baseline: 1.0648x; 1.0648x over previous
#include <cuda_runtime.h>

// Depth-3 sliding-window path signature via Chen-identity chunk factorization.
// B=256, L=2048, C=6, WIN=64, STRIDE=32 -> 63 windows / batch.
//
// window_w (63 incr) = chunk_w(32 incr) (x) [chunk_{w+1} minus last incr]
//                    = A_w (x) A_{w+1} (x) exp(-d_last(w+1))
//
// Kernel A: 64 disjoint chunk signatures per batch, 32 sequential steps each
//           (chunk 63 zero-padded: exp(0)=identity). -> global scratch.
// Kernel B: per (b,w,i): two Chen combines, write output.
// All state kept pre-scaled: S2 = 2*s2, S3 = 6*s3 (matches output scaling).

namespace {

constexpr int BATCH = 256;
constexpr int LEN   = 2048;
constexpr int CH    = 6;
constexpr int NW    = 63;
constexpr int NCHUNK = 64;
constexpr int NCOMP  = 43;          // 1 + 6 + 36 per lane
constexpr int COLS   = NCHUNK * CH; // 384 columns per (b, comp)

// scratch: gsig[b][comp][chunk*6+i]
__device__ float g_sig[BATCH * NCOMP * COLS];

// ---------------- Kernel A: chunk scans ----------------
// grid = 1024 (= batch*4 groups), block = 96 (= 16 chunks * 6 lanes)
constexpr int GROUPS = 4;
constexpr int CPG    = 16;          // chunks per group
constexpr int TA     = CPG * CH;    // 96 threads
constexpr int LPG    = CPG * 32;    // 512 increments per group
constexpr int SROWA  = 529;         // odd padded row stride (512 + 16 pad, odd)

__global__ __launch_bounds__(TA, 8)
void scan_kernel(const float* __restrict__ path) {
    __shared__ float s_dx[CH * SROWA];

    const int tid = threadIdx.x;
    const int b   = blockIdx.x >> 2;
    const int g   = blockIdx.x & 3;
    const int l0  = g * LPG;
    const float* __restrict__ row = path + (long long)b * (LEN * CH);

    // Stage increments (zero-fill past l=2046 so chunk 63 runs 32 uniform steps).
    for (int idx = tid; idx < LPG * CH; idx += TA) {
        const int l = idx / CH;
        const int c = idx - l * CH;
        float d = 0.0f;
        if (l0 + l < LEN - 1) {
            const int gi = (l0 + l) * CH + c;
            d = row[gi + CH] - row[gi];
        }
        s_dx[c * SROWA + l + (l >> 5)] = d;
    }
    __syncthreads();

    const int ml = tid / CH;        // local chunk 0..15
    const int i  = tid - ml * CH;   // leading channel
    const int base = 33 * ml;       // padded offset of local l = 32*ml

    float s1 = 0.0f;
    float S2[6];
    float S3[6][6];
#pragma unroll
    for (int j = 0; j < 6; ++j) {
        S2[j] = 0.0f;
#pragma unroll
        for (int k = 0; k < 6; ++k) S3[j][k] = 0.0f;
    }

    const float* __restrict__ rowi = s_dx + i * SROWA;

#pragma unroll 8
    for (int t = 0; t < 32; ++t) {
        const int off = base + t;   // t<32 -> no extra pad term
        float d[6];
        d[0] = s_dx[0 * SROWA + off];
        d[1] = s_dx[1 * SROWA + off];
        d[2] = s_dx[2 * SROWA + off];
        d[3] = s_dx[3 * SROWA + off];
        d[4] = s_dx[4 * SROWA + off];
        d[5] = s_dx[5 * SROWA + off];
        const float di = rowi[off];

        const float a  = fmaf(3.0f, s1, di);   // old s1
        const float b2 = fmaf(2.0f, s1, di);

#pragma unroll
        for (int j = 0; j < 6; ++j) {
            const float coef = fmaf(3.0f, S2[j], a * d[j]);  // old S2
#pragma unroll
            for (int k = 0; k < 6; ++k)
                S3[j][k] = fmaf(coef, d[k], S3[j][k]);
        }
#pragma unroll
        for (int j = 0; j < 6; ++j) S2[j] = fmaf(b2, d[j], S2[j]);
        s1 += di;
    }

    // Write lane state: column = chunk*6 + i ; coalesced per comp.
    float* __restrict__ o = g_sig + b * (NCOMP * COLS);
    const int col = (g * CPG + ml) * CH + i;
    o[col] = s1;
#pragma unroll
    for (int j = 0; j < 6; ++j) o[(1 + j) * COLS + col] = S2[j];
#pragma unroll
    for (int j = 0; j < 6; ++j)
#pragma unroll
        for (int k = 0; k < 6; ++k) o[(7 + j * 6 + k) * COLS + col] = S3[j][k];
}

// ---------------- Kernel B: combine ----------------
// out_w = (A_w (x) A_{w+1}) (x) exp(-d),  d = increment at l = 32w+63 (0 for w=62)
// grid = 252, block = 384 -> exactly 256*63*6 threads.
constexpr int TB = 384;

__global__ __launch_bounds__(TB)
void combine_kernel(const float* __restrict__ path, float* __restrict__ out) {
    const int gidx = blockIdx.x * TB + threadIdx.x;
    const int b = gidx / (NW * CH);
    const int r = gidx - b * (NW * CH);
    const int w = r / CH;
    const int i = r - w * CH;

    const float* __restrict__ A = g_sig + b * (NCOMP * COLS);
    const int ca  = w * CH + i;        // A_w,  lane i
    const int cb0 = (w + 1) * CH;      // A_{w+1}, lane base
    const int cbi = cb0 + i;           // A_{w+1}, lane i

    const float a1 = A[ca];
    float b1[6];
#pragma unroll
    for (int j = 0; j < 6; ++j) b1[j] = A[cb0 + j];

    float d[6];
    if (w < NW - 1) {
        const float* __restrict__ p =
            path + ((long long)b * LEN + (32 * w + 63)) * CH;
#pragma unroll
        for (int c = 0; c < 6; ++c) d[c] = p[c + CH] - p[c];
    } else {
#pragma unroll
        for (int c = 0; c < 6; ++c) d[c] = 0.0f;
    }

    const float m1 = a1 + b1[i];

    // M2 row i (scaled 2x):  M2[j] = A2[i][j] + B2[i][j] + 2 a1 b1[j]
    float A2r[6], M2[6];
#pragma unroll
    for (int j = 0; j < 6; ++j) {
        A2r[j] = A[(1 + j) * COLS + ca];
        M2[j]  = A2r[j] + A[(1 + j) * COLS + cbi] + 2.0f * a1 * b1[j];
    }

    float* __restrict__ o = out + ((long long)b * NW + w) * 258;

    // level 1
    o[i] = m1 - d[i];
    // level 2 (scaled 2x): out = M2 + (d_i - 2 m1) d_j
    const float c2 = d[i] - 2.0f * m1;
#pragma unroll
    for (int j = 0; j < 6; ++j) o[6 + i * 6 + j] = fmaf(c2, d[j], M2[j]);

    // level 3 (scaled 6x):
    // M3[j][k] = A3 + B3 + 3 A2[i][j] b1[k] + 3 a1 B2[j][k]
    // out3     = M3 + (3 m1 d_j - d_i d_j - 3 M2[j]) d_k
    const float t3a1 = 3.0f * a1;
    const float c3   = 3.0f * m1 - d[i];
#pragma unroll
    for (int j = 0; j < 6; ++j) {
        const float a2b = 3.0f * A2r[j];
        const float coef = fmaf(c3, d[j], -3.0f * M2[j]);
#pragma unroll
        for (int k = 0; k < 6; ++k) {
            float v = A[(7 + j * 6 + k) * COLS + ca]
                    + A[(7 + j * 6 + k) * COLS + cbi];
            v = fmaf(a2b, b1[k], v);
            v = fmaf(t3a1, A[(1 + k) * COLS + cb0 + j], v);  // 3 a1 B2[j][k]
            o[42 + i * 36 + j * 6 + k] = fmaf(coef, d[k], v);
        }
    }
}

}  // namespace

extern "C" void kernel_launch(void* const* d_in, const int* in_sizes, int n_in,
                              void* d_out, int out_size) {
    const float* path = (const float*)d_in[0];
    float* out = (float*)d_out;
    scan_kernel<<<BATCH * GROUPS, TA>>>(path);
    combine_kernel<<<(BATCH * NW * CH) / TB, TB>>>(path, out);
}

// round 3
// speedup vs baseline: 1.2468x; 1.1709x over previous
#include <cuda_runtime.h>

// Fused depth-3 sliding-window path signature (Chen chunk factorization).
// B=256, L=2048, C=6, WIN=64, STRIDE=32 -> 63 windows / batch.
// One block per batch, 384 threads = 64 chunks x 6 leading-channel lanes.
//   phase 1: stage increments dx into smem (padded, zero-filled tail)
//   phase 2: each lane scans its 32-increment chunk (state in 43 regs)
//   phase 3: lane (w,i) snapshots d_last = dx[32w+63] for the exp(-d) correction
//   phase 4: chunk states -> smem (aliases dx region), sync
//   phase 5: window_w = A_w (x) A_{w+1} (x) exp(-d_last), all reads from smem
// State pre-scaled: S2 = 2*s2, S3 = 6*s3 (matches required output scaling).

namespace {

constexpr int BATCH   = 256;
constexpr int LEN     = 2048;
constexpr int CH      = 6;
constexpr int NW      = 63;
constexpr int THREADS = 384;
constexpr int SROWD   = 2111;              // dx row stride (2047+63 pad, odd)
constexpr int SCOL    = 385;               // sig column stride (384 lanes + pad)
constexpr int SIG_FLOATS = 43 * SCOL;      // 16555 > 6*SROWD=12666
constexpr int SMEM_BYTES = SIG_FLOATS * (int)sizeof(float);  // 66220 B

__global__ __launch_bounds__(THREADS, 2)
void fused_kernel(const float* __restrict__ path, float* __restrict__ out) {
    extern __shared__ float sm[];
    float* __restrict__ s_dx  = sm;   // phase 1-3: [CH][SROWD], l at l+(l>>5)
    float* __restrict__ s_sig = sm;   // phase 4-5: [43][SCOL]   (aliases dx)

    const int tid = threadIdx.x;
    const int b   = blockIdx.x;
    const float* __restrict__ row = path + (long long)b * (LEN * CH);

    // ---- phase 1: stage increments (zero past l=2046) ----
    for (int idx = tid; idx < 2048 * CH; idx += THREADS) {
        const int l = idx / CH;
        const int c = idx - l * CH;
        float d = 0.0f;
        if (l < LEN - 1) d = row[idx + CH] - row[idx];
        s_dx[c * SROWD + l + (l >> 5)] = d;
    }
    __syncthreads();

    // ---- phase 2: chunk scan (chunk m = increments l = 32m .. 32m+31) ----
    const int m = tid / CH;        // chunk 0..63
    const int i = tid - m * CH;    // leading channel
    const int base = 33 * m;       // padded offset of l = 32m

    float s1 = 0.0f;
    float S2[6];
    float S3[6][6];
#pragma unroll
    for (int j = 0; j < 6; ++j) {
        S2[j] = 0.0f;
#pragma unroll
        for (int k = 0; k < 6; ++k) S3[j][k] = 0.0f;
    }

    const float* __restrict__ rowi = s_dx + i * SROWD;

#pragma unroll 4
    for (int t = 0; t < 32; ++t) {
        const int off = base + t;          // t<32: no extra pad term
        float d[6];
        d[0] = s_dx[0 * SROWD + off];
        d[1] = s_dx[1 * SROWD + off];
        d[2] = s_dx[2 * SROWD + off];
        d[3] = s_dx[3 * SROWD + off];
        d[4] = s_dx[4 * SROWD + off];
        d[5] = s_dx[5 * SROWD + off];
        const float di = rowi[off];

        const float a  = fmaf(3.0f, s1, di);   // old s1
        const float b2 = fmaf(2.0f, s1, di);

#pragma unroll
        for (int j = 0; j < 6; ++j) {
            const float coef = fmaf(3.0f, S2[j], a * d[j]);  // old S2
#pragma unroll
            for (int k = 0; k < 6; ++k)
                S3[j][k] = fmaf(coef, d[k], S3[j][k]);
        }
#pragma unroll
        for (int j = 0; j < 6; ++j) S2[j] = fmaf(b2, d[j], S2[j]);
        s1 += di;
    }

    // ---- phase 3: snapshot d_last for window w=m (l = 32w+63, valid w<62) ----
    float dc[6];
#pragma unroll
    for (int c = 0; c < 6; ++c) dc[c] = 0.0f;
    if (m < NW - 1) {
        const int off = 33 * m + 64;       // (32m+63) + ((32m+63)>>5)
#pragma unroll
        for (int c = 0; c < 6; ++c) dc[c] = s_dx[c * SROWD + off];
    }
    __syncthreads();   // all dx reads complete before overwrite

    // ---- phase 4: publish chunk state (column = tid = m*6+i) ----
    s_sig[tid] = s1;
#pragma unroll
    for (int j = 0; j < 6; ++j) s_sig[(1 + j) * SCOL + tid] = S2[j];
#pragma unroll
    for (int j = 0; j < 6; ++j)
#pragma unroll
        for (int k = 0; k < 6; ++k) s_sig[(7 + j * 6 + k) * SCOL + tid] = S3[j][k];
    __syncthreads();

    // ---- phase 5: combine. window w = m (m<63), lane i ----
    if (m >= NW) return;   // chunk-63 lanes done
    const int w   = m;
    const int ca  = tid;               // A_w   lane i
    const int cb0 = (w + 1) * CH;      // A_{w+1} lane base
    const int cbi = cb0 + i;

    const float a1 = s_sig[ca];
    float b1[6];
#pragma unroll
    for (int j = 0; j < 6; ++j) b1[j] = s_sig[cb0 + j];

    const float m1 = a1 + b1[i];

    // M2 row i (2x scale): M2[j] = A2[i][j] + B2[i][j] + 2 a1 b1[j]
    float A2r[6], M2[6];
#pragma unroll
    for (int j = 0; j < 6; ++j) {
        A2r[j] = s_sig[(1 + j) * SCOL + ca];
        M2[j]  = A2r[j] + s_sig[(1 + j) * SCOL + cbi] + 2.0f * a1 * b1[j];
    }

    float* __restrict__ o = out + ((long long)b * NW + w) * 258;

    // level 1: subtract trailing increment
    o[i] = m1 - dc[i];

    // level 2 (2x): out = M2 + (d_i - 2 m1) d_j
    const float c2 = dc[i] - 2.0f * m1;
#pragma unroll
    for (int j = 0; j < 6; ++j) o[6 + i * 6 + j] = fmaf(c2, dc[j], M2[j]);

    // level 3 (6x):
    //   M3[j][k] = A3 + B3 + 3 A2[i][j] b1[k] + 3 a1 B2[j][k]
    //   out3     = M3 + (3 m1 d_j - d_i d_j - 3 M2[j]) d_k
    const float t3a1 = 3.0f * a1;
    const float c3   = 3.0f * m1 - dc[i];
#pragma unroll
    for (int j = 0; j < 6; ++j) {
        const float a2b  = 3.0f * A2r[j];
        const float coef = fmaf(c3, dc[j], -3.0f * M2[j]);
#pragma unroll
        for (int k = 0; k < 6; ++k) {
            float v = s_sig[(7 + j * 6 + k) * SCOL + ca]
                    + s_sig[(7 + j * 6 + k) * SCOL + cbi];
            v = fmaf(a2b, b1[k], v);
            v = fmaf(t3a1, s_sig[(1 + k) * SCOL + cb0 + j], v);  // 3 a1 B2[j][k]
            o[42 + i * 36 + j * 6 + k] = fmaf(coef, dc[k], v);
        }
    }
}

}  // namespace

extern "C" void kernel_launch(void* const* d_in, const int* in_sizes, int n_in,
                              void* d_out, int out_size) {
    const float* path = (const float*)d_in[0];
    float* out = (float*)d_out;
    cudaFuncSetAttribute(fused_kernel, cudaFuncAttributeMaxDynamicSharedMemorySize,
                         SMEM_BYTES);
    fused_kernel<<<BATCH, THREADS, SMEM_BYTES>>>(path, out);
}

// round 4
// speedup vs baseline: 1.2795x; 1.0263x over previous
#include <cuda_runtime.h>

// Fused depth-3 sliding-window path signature (Chen chunk factorization),
// split 4 ways per batch for occupancy/balance.
// B=256, L=2048, C=6, WIN=64, STRIDE=32 -> 63 windows / batch.
//
// Grid = 1024 blocks (batch b = blk/4, quarter g = blk%4), 128 threads.
// Block (b,g):
//   stage:   increments l in [512g, 512g+544) -> smem (zero-fill l >= 2047)
//   scan:    17 chunks (global chunks 16g..16g+16), 32 steps each, 102 threads
//   combine: windows w = 16g..16g+15 (skip w=63): A_w (x) A_{w+1} (x) exp(-d)
// State pre-scaled: S2 = 2*s2, S3 = 6*s3 (matches output scaling).
// Zero-filled dx tail makes chunk-64 = identity and d_last(w=62) = 0 branch-free.

namespace {

constexpr int BATCH   = 256;
constexpr int LEN     = 2048;
constexpr int CH      = 6;
constexpr int NW      = 63;
constexpr int THREADS = 128;
constexpr int NCHUNKL = 17;               // chunks per block (1 overlap)
constexpr int NWL     = 16;               // windows per block
constexpr int NDXL    = 544;              // staged increments per block
constexpr int SROWD   = 561;              // dx row stride (544 + 17 pad, odd)
constexpr int NLANE   = NCHUNKL * CH;     // 102 scan lanes
constexpr int SCOL    = 103;              // sig column stride (102 + 1, odd)
constexpr int SM_FLOATS = 43 * SCOL;      // 4429 >= 6*SROWD = 3366

__global__ __launch_bounds__(THREADS, 7)
void fused_kernel(const float* __restrict__ path, float* __restrict__ out) {
    __shared__ float sm[SM_FLOATS];
    float* __restrict__ s_dx  = sm;   // stage/scan: [CH][SROWD], l' at l'+(l'>>5)
    float* __restrict__ s_sig = sm;   // publish/combine: [43][SCOL] (aliases dx)

    const int tid = threadIdx.x;
    const int b   = blockIdx.x >> 2;
    const int g   = blockIdx.x & 3;
    const int l0  = g * 512;
    const float* __restrict__ row = path + (long long)b * (LEN * CH);

    // ---- stage increments: local l' = 0..543, global l = l0 + l' ----
    for (int idx = tid; idx < NDXL * CH; idx += THREADS) {
        const int l = idx / CH;
        const int c = idx - l * CH;
        float d = 0.0f;
        const int gl = l0 + l;
        if (gl < LEN - 1) {
            const int gi = gl * CH + c;
            d = row[gi + CH] - row[gi];
        }
        s_dx[c * SROWD + l + (l >> 5)] = d;
    }
    __syncthreads();

    // ---- scan: local chunk mc = tid/6 in [0,17), leading channel i ----
    const int mc = tid / CH;
    const int i  = tid - mc * CH;
    const bool scan_lane = (tid < NLANE);

    float s1 = 0.0f;
    float S2[6];
    float S3[6][6];
#pragma unroll
    for (int j = 0; j < 6; ++j) {
        S2[j] = 0.0f;
#pragma unroll
        for (int k = 0; k < 6; ++k) S3[j][k] = 0.0f;
    }

    if (scan_lane) {
        const int base = 33 * mc;   // padded offset of local l' = 32*mc
        const float* __restrict__ rowi = s_dx + i * SROWD;

#pragma unroll 4
        for (int t = 0; t < 32; ++t) {
            const int off = base + t;       // t<32: no extra pad term
            float d[6];
            d[0] = s_dx[0 * SROWD + off];
            d[1] = s_dx[1 * SROWD + off];
            d[2] = s_dx[2 * SROWD + off];
            d[3] = s_dx[3 * SROWD + off];
            d[4] = s_dx[4 * SROWD + off];
            d[5] = s_dx[5 * SROWD + off];
            const float di = rowi[off];

            const float a  = fmaf(3.0f, s1, di);   // old s1
            const float b2 = fmaf(2.0f, s1, di);

#pragma unroll
            for (int j = 0; j < 6; ++j) {
                const float coef = fmaf(3.0f, S2[j], a * d[j]);  // old S2
#pragma unroll
                for (int k = 0; k < 6; ++k)
                    S3[j][k] = fmaf(coef, d[k], S3[j][k]);
            }
#pragma unroll
            for (int j = 0; j < 6; ++j) S2[j] = fmaf(b2, d[j], S2[j]);
            s1 += di;
        }
    }

    // ---- snapshot d_last for local window wl = mc (< 16):
    //      global l = 32(16g+wl)+63 -> local l' = 32*wl + 63, padded +((..)>>5)
    float dc[6];
    {
        const int off = 33 * mc + 64;       // = (32mc+63) + ((32mc+63)>>5)
        const bool cw = (mc < NWL);
#pragma unroll
        for (int c = 0; c < 6; ++c) dc[c] = cw ? s_dx[c * SROWD + off] : 0.0f;
    }
    __syncthreads();   // all dx reads done before overwrite

    // ---- publish chunk state: column = tid (stride-1 across threads) ----
    if (scan_lane) {
        s_sig[tid] = s1;
#pragma unroll
        for (int j = 0; j < 6; ++j) s_sig[(1 + j) * SCOL + tid] = S2[j];
#pragma unroll
        for (int j = 0; j < 6; ++j)
#pragma unroll
            for (int k = 0; k < 6; ++k)
                s_sig[(7 + j * 6 + k) * SCOL + tid] = S3[j][k];
    }
    __syncthreads();

    // ---- combine: local window wl = mc (< 16), global w = 16g + wl ----
    const int w = NWL * g + mc;
    if (mc >= NWL || w >= NW) return;

    const int ca  = tid;                 // A_w lane i   (= mc*6+i)
    const int cb0 = (mc + 1) * CH;       // A_{w+1} lane base
    const int cbi = cb0 + i;

    const float a1 = s_sig[ca];
    float b1[6];
#pragma unroll
    for (int j = 0; j < 6; ++j) b1[j] = s_sig[cb0 + j];

    const float m1 = a1 + b1[i];

    // M2 row i (2x): M2[j] = A2[i][j] + B2[i][j] + 2 a1 b1[j]
    float A2r[6], M2[6];
#pragma unroll
    for (int j = 0; j < 6; ++j) {
        A2r[j] = s_sig[(1 + j) * SCOL + ca];
        M2[j]  = A2r[j] + s_sig[(1 + j) * SCOL + cbi] + 2.0f * a1 * b1[j];
    }

    float* __restrict__ o = out + ((long long)b * NW + w) * 258;

    // level 1
    o[i] = m1 - dc[i];

    // level 2 (2x): out = M2 + (d_i - 2 m1) d_j
    const float c2 = dc[i] - 2.0f * m1;
#pragma unroll
    for (int j = 0; j < 6; ++j) o[6 + i * 6 + j] = fmaf(c2, dc[j], M2[j]);

    // level 3 (6x):
    //   M3[j][k] = A3 + B3 + 3 A2[i][j] b1[k] + 3 a1 B2[j][k]
    //   out3     = M3 + (3 m1 d_j - d_i d_j - 3 M2[j]) d_k
    const float t3a1 = 3.0f * a1;
    const float c3   = 3.0f * m1 - dc[i];
#pragma unroll
    for (int j = 0; j < 6; ++j) {
        const float a2b  = 3.0f * A2r[j];
        const float coef = fmaf(c3, dc[j], -3.0f * M2[j]);
#pragma unroll
        for (int k = 0; k < 6; ++k) {
            float v = s_sig[(7 + j * 6 + k) * SCOL + ca]
                    + s_sig[(7 + j * 6 + k) * SCOL + cbi];
            v = fmaf(a2b, b1[k], v);
            v = fmaf(t3a1, s_sig[(1 + k) * SCOL + cb0 + j], v);  // 3 a1 B2[j][k]
            o[42 + i * 36 + j * 6 + k] = fmaf(coef, dc[k], v);
        }
    }
}

}  // namespace

extern "C" void kernel_launch(void* const* d_in, const int* in_sizes, int n_in,
                              void* d_out, int out_size) {
    const float* path = (const float*)d_in[0];
    float* out = (float*)d_out;
    fused_kernel<<<BATCH * 4, THREADS>>>(path, out);
}

// round 7
// speedup vs baseline: 1.3778x; 1.0768x over previous
#include <cuda_runtime.h>

// Fused depth-3 sliding-window path signature (Chen chunk factorization).
// B=256, L=2048, C=6, WIN=64, STRIDE=32 -> 63 windows / batch.
// Grid = 1024 blocks (batch = blk/4, quarter g = blk%4), 128 threads.
// Scan state: s1, T2 = 3*2*s2 (= 3*S2), S3 = 6*s3. Rescaled T2 makes the
// per-step coef a single FMA: coef_j = a*d_j + T2[j].
// dx staged as 3 float2 rows (channel pairs) -> 3 LDS.64 + 1 LDS.32 per step.

namespace {

constexpr int BATCH   = 256;
constexpr int LEN     = 2048;
constexpr int CH      = 6;
constexpr int NW      = 63;
constexpr int THREADS = 128;
constexpr int NCHUNKL = 17;               // chunks per block (1 overlap)
constexpr int NWL     = 16;               // windows per block
constexpr int NDXL    = 544;              // staged increments per block
constexpr int SROWD2  = 561;              // float2 row stride (544+17 pad, odd)
constexpr int NLANE   = NCHUNKL * CH;     // 102 scan lanes
constexpr int SCOL    = 103;              // sig column stride
constexpr int SM_FLOATS = 43 * SCOL;      // 4429 >= 3*SROWD2*2 = 3366

__global__ __launch_bounds__(THREADS, 7)
void fused_kernel(const float* __restrict__ path, float* __restrict__ out) {
    __shared__ __align__(16) float sm[SM_FLOATS];
    float2* __restrict__ s_dx2 = reinterpret_cast<float2*>(sm); // [3][SROWD2]
    float*  __restrict__ s_sig = sm;                            // [43][SCOL]

    const int tid = threadIdx.x;
    const int b   = blockIdx.x >> 2;
    const int g   = blockIdx.x & 3;
    const int l0  = g * 512;
    const float2* __restrict__ rowv =
        reinterpret_cast<const float2*>(path + (long long)b * (LEN * CH));
    // rowv[l*3 + pr] = channels (2pr, 2pr+1) at time l.

    // ---- stage increments as float2 (zero-fill global l >= 2047) ----
    for (int idx = tid; idx < NDXL * 3; idx += THREADS) {
        const int l  = idx / 3;
        const int pr = idx - l * 3;
        float2 d2 = make_float2(0.0f, 0.0f);
        const int gl = l0 + l;
        if (gl < LEN - 1) {
            const float2 v0 = rowv[gl * 3 + pr];
            const float2 v1 = rowv[gl * 3 + 3 + pr];
            d2.x = v1.x - v0.x;
            d2.y = v1.y - v0.y;
        }
        s_dx2[pr * SROWD2 + l + (l >> 5)] = d2;
    }
    __syncthreads();

    const int mc = tid / CH;       // local chunk 0..16 (or >16 idle-ish lanes)
    const int i  = tid - mc * CH;  // leading channel
    const bool scan_lane = (tid < NLANE);

    float s1 = 0.0f;
    float T2[6];                   // 3 * S2  (S2 = 2*s2)
    float S3[6][6];                // 6 * s3
#pragma unroll
    for (int j = 0; j < 6; ++j) {
        T2[j] = 0.0f;
#pragma unroll
        for (int k = 0; k < 6; ++k) S3[j][k] = 0.0f;
    }

    if (scan_lane) {
        const int base = 33 * mc;  // padded float2 offset of local l = 32*mc
        // di = channel i: float word index 2*(pr_i*SROWD2 + off) + (i&1)
        const float* __restrict__ rowi = sm + 2 * (i >> 1) * SROWD2 + (i & 1);

#pragma unroll 4
        for (int t = 0; t < 32; ++t) {
            const int off = base + t;            // t<32: no extra pad term
            const float2 d01 = s_dx2[0 * SROWD2 + off];
            const float2 d23 = s_dx2[1 * SROWD2 + off];
            const float2 d45 = s_dx2[2 * SROWD2 + off];
            const float di = rowi[2 * off];

            const float a   = fmaf(3.0f, s1, di);          // di + 3 s1 (old s1)
            const float b23 = fmaf(6.0f, s1, 3.0f * di);   // 3*(di + 2 s1)

            const float d[6] = {d01.x, d01.y, d23.x, d23.y, d45.x, d45.y};

            float coef[6];                                  // uses old T2
#pragma unroll
            for (int j = 0; j < 6; ++j) coef[j] = fmaf(a, d[j], T2[j]);

#pragma unroll
            for (int j = 0; j < 6; ++j)
#pragma unroll
                for (int k = 0; k < 6; ++k)
                    S3[j][k] = fmaf(coef[j], d[k], S3[j][k]);

#pragma unroll
            for (int j = 0; j < 6; ++j) T2[j] = fmaf(b23, d[j], T2[j]);
            s1 += di;
        }
    }

    // ---- snapshot d_last for local window wl = mc (l' = 32mc+63) ----
    float dc[6];
    {
        const int off = 33 * mc + 64;            // (32mc+63) + ((32mc+63)>>5)
        const bool cw = (mc < NWL);
        float2 c01 = make_float2(0.0f, 0.0f), c23 = c01, c45 = c01;
        if (cw) {
            c01 = s_dx2[0 * SROWD2 + off];
            c23 = s_dx2[1 * SROWD2 + off];
            c45 = s_dx2[2 * SROWD2 + off];
        }
        dc[0] = c01.x; dc[1] = c01.y; dc[2] = c23.x;
        dc[3] = c23.y; dc[4] = c45.x; dc[5] = c45.y;
    }
    __syncthreads();   // all dx reads done before s_sig overwrites

    // ---- publish chunk state: S2 = T2/3, column = tid ----
    if (scan_lane) {
        s_sig[tid] = s1;
        const float third = 1.0f / 3.0f;
#pragma unroll
        for (int j = 0; j < 6; ++j) s_sig[(1 + j) * SCOL + tid] = T2[j] * third;
#pragma unroll
        for (int j = 0; j < 6; ++j)
#pragma unroll
            for (int k = 0; k < 6; ++k)
                s_sig[(7 + j * 6 + k) * SCOL + tid] = S3[j][k];
    }
    __syncthreads();

    // ---- combine: window w = 16g + mc;  out = A_w (x) A_{w+1} (x) exp(-dc) ----
    const int w = NWL * g + mc;
    if (mc >= NWL || w >= NW) return;

    const int ca  = tid;               // A_w lane i
    const int cb0 = (mc + 1) * CH;     // A_{w+1} lane base
    const int cbi = cb0 + i;

    const float a1 = s_sig[ca];
    float b1[6];
#pragma unroll
    for (int j = 0; j < 6; ++j) b1[j] = s_sig[cb0 + j];

    const float m1 = a1 + b1[i];

    // M2 row i (2x scale): M2[j] = A2[i][j] + B2[i][j] + 2 a1 b1[j]
    float A2r[6], M2[6];
#pragma unroll
    for (int j = 0; j < 6; ++j) {
        A2r[j] = s_sig[(1 + j) * SCOL + ca];
        M2[j]  = A2r[j] + s_sig[(1 + j) * SCOL + cbi] + 2.0f * a1 * b1[j];
    }

    float* __restrict__ o = out + ((long long)b * NW + w) * 258;

    // level 1
    o[i] = m1 - dc[i];

    // level 2 (2x): out = M2 + (d_i - 2 m1) d_j
    const float c2 = dc[i] - 2.0f * m1;
#pragma unroll
    for (int j = 0; j < 6; ++j) o[6 + i * 6 + j] = fmaf(c2, dc[j], M2[j]);

    // level 3 (6x):
    //   M3[j][k] = A3 + B3 + 3 A2[i][j] b1[k] + 3 a1 B2[j][k]
    //   out3     = M3 + (3 m1 d_j - d_i d_j - 3 M2[j]) d_k
    const float t3a1 = 3.0f * a1;
    const float c3   = 3.0f * m1 - dc[i];
#pragma unroll
    for (int j = 0; j < 6; ++j) {
        const float a2b  = 3.0f * A2r[j];
        const float coef = fmaf(c3, dc[j], -3.0f * M2[j]);
#pragma unroll
        for (int k = 0; k < 6; ++k) {
            float v = s_sig[(7 + j * 6 + k) * SCOL + ca]
                    + s_sig[(7 + j * 6 + k) * SCOL + cbi];
            v = fmaf(a2b, b1[k], v);
            v = fmaf(t3a1, s_sig[(1 + k) * SCOL + cb0 + j], v);  // 3 a1 B2[j][k]
            o[42 + i * 36 + j * 6 + k] = fmaf(coef, dc[k], v);
        }
    }
}

}  // namespace

extern "C" void kernel_launch(void* const* d_in, const int* in_sizes, int n_in,
                              void* d_out, int out_size) {
    const float* path = (const float*)d_in[0];
    float* out = (float*)d_out;
    fused_kernel<<<BATCH * 4, THREADS>>>(path, out);
}

// round 8
// speedup vs baseline: 2.0698x; 1.5023x over previous
#include <cuda_runtime.h>

// Fused depth-3 sliding-window path signature (Chen chunk factorization),
// with smem-staged coalesced output.
// B=256, L=2048, C=6, WIN=64, STRIDE=32 -> 63 windows / batch.
// Grid = 1024 blocks (batch = blk/4, quarter g = blk%4), 128 threads.
// Scan state: s1, T2 = 3*(2*s2), S3 = 6*s3. coef_j = a*d_j + T2[j] (1 FMA).
// dx staged as 3 float2 rows -> 3 LDS.64 + 1 LDS.32 per scan step.
// Output: combine -> regs -> smem [wl][258] -> coalesced block copy to global.

namespace {

constexpr int BATCH   = 256;
constexpr int LEN     = 2048;
constexpr int CH      = 6;
constexpr int NW      = 63;
constexpr int THREADS = 128;
constexpr int NCHUNKL = 17;               // chunks per block (1 overlap)
constexpr int NWL     = 16;               // windows per block
constexpr int NDXL    = 544;              // staged increments per block
constexpr int SROWD2  = 561;              // float2 row stride (544+17 pad, odd)
constexpr int NLANE   = NCHUNKL * CH;     // 102 scan lanes
constexpr int SCOL    = 103;              // sig column stride
constexpr int SM_FLOATS = 43 * SCOL;      // 4429 >= max(3*561*2, 16*258)

__global__ __launch_bounds__(THREADS, 7)
void fused_kernel(const float* __restrict__ path, float* __restrict__ out) {
    __shared__ __align__(16) float sm[SM_FLOATS];
    float2* __restrict__ s_dx2 = reinterpret_cast<float2*>(sm); // [3][SROWD2]
    float*  __restrict__ s_sig = sm;                            // [43][SCOL]

    const int tid = threadIdx.x;
    const int b   = blockIdx.x >> 2;
    const int g   = blockIdx.x & 3;
    const int l0  = g * 512;
    const float2* __restrict__ rowv =
        reinterpret_cast<const float2*>(path + (long long)b * (LEN * CH));
    // rowv[l*3 + pr] = channels (2pr, 2pr+1) at time l.

    // ---- stage increments as float2 (zero-fill global l >= 2047) ----
    for (int idx = tid; idx < NDXL * 3; idx += THREADS) {
        const int l  = idx / 3;
        const int pr = idx - l * 3;
        float2 d2 = make_float2(0.0f, 0.0f);
        const int gl = l0 + l;
        if (gl < LEN - 1) {
            const float2 v0 = rowv[gl * 3 + pr];
            const float2 v1 = rowv[gl * 3 + 3 + pr];
            d2.x = v1.x - v0.x;
            d2.y = v1.y - v0.y;
        }
        s_dx2[pr * SROWD2 + l + (l >> 5)] = d2;
    }
    __syncthreads();

    const int mc = tid / CH;       // local chunk 0..16 (tid>=102: idle lanes)
    const int i  = tid - mc * CH;  // leading channel
    const bool scan_lane = (tid < NLANE);

    float s1 = 0.0f;
    float T2[6];                   // 3 * S2  (S2 = 2*s2)
    float S3[6][6];                // 6 * s3
#pragma unroll
    for (int j = 0; j < 6; ++j) {
        T2[j] = 0.0f;
#pragma unroll
        for (int k = 0; k < 6; ++k) S3[j][k] = 0.0f;
    }

    if (scan_lane) {
        const int base = 33 * mc;  // padded float2 offset of local l = 32*mc
        const float* __restrict__ rowi = sm + 2 * (i >> 1) * SROWD2 + (i & 1);

#pragma unroll 4
        for (int t = 0; t < 32; ++t) {
            const int off = base + t;            // t<32: no extra pad term
            const float2 d01 = s_dx2[0 * SROWD2 + off];
            const float2 d23 = s_dx2[1 * SROWD2 + off];
            const float2 d45 = s_dx2[2 * SROWD2 + off];
            const float di = rowi[2 * off];

            const float a   = fmaf(3.0f, s1, di);          // di + 3 s1 (old s1)
            const float b23 = fmaf(6.0f, s1, 3.0f * di);   // 3*(di + 2 s1)

            const float d[6] = {d01.x, d01.y, d23.x, d23.y, d45.x, d45.y};

            float coef[6];                                  // uses old T2
#pragma unroll
            for (int j = 0; j < 6; ++j) coef[j] = fmaf(a, d[j], T2[j]);

#pragma unroll
            for (int j = 0; j < 6; ++j)
#pragma unroll
                for (int k = 0; k < 6; ++k)
                    S3[j][k] = fmaf(coef[j], d[k], S3[j][k]);

#pragma unroll
            for (int j = 0; j < 6; ++j) T2[j] = fmaf(b23, d[j], T2[j]);
            s1 += di;
        }
    }

    // ---- snapshot d_last for local window wl = mc (l' = 32mc+63) ----
    float dc[6];
    {
        const int off = 33 * mc + 64;            // (32mc+63) + ((32mc+63)>>5)
        const bool cw = (mc < NWL);
        float2 c01 = make_float2(0.0f, 0.0f), c23 = c01, c45 = c01;
        if (cw) {
            c01 = s_dx2[0 * SROWD2 + off];
            c23 = s_dx2[1 * SROWD2 + off];
            c45 = s_dx2[2 * SROWD2 + off];
        }
        dc[0] = c01.x; dc[1] = c01.y; dc[2] = c23.x;
        dc[3] = c23.y; dc[4] = c45.x; dc[5] = c45.y;
    }
    __syncthreads();   // all dx reads done before s_sig overwrites

    // ---- publish chunk state: S2 = T2/3, column = tid ----
    if (scan_lane) {
        s_sig[tid] = s1;
        const float third = 1.0f / 3.0f;
#pragma unroll
        for (int j = 0; j < 6; ++j) s_sig[(1 + j) * SCOL + tid] = T2[j] * third;
#pragma unroll
        for (int j = 0; j < 6; ++j)
#pragma unroll
            for (int k = 0; k < 6; ++k)
                s_sig[(7 + j * 6 + k) * SCOL + tid] = S3[j][k];
    }
    __syncthreads();

    // ---- combine into registers: window w = 16g + mc ----
    const int w = NWL * g + mc;
    const bool cw = (mc < NWL) && (w < NW);

    float r1 = 0.0f, r2[6], r3[6][6];
    if (cw) {
        const int ca  = tid;               // A_w lane i
        const int cb0 = (mc + 1) * CH;     // A_{w+1} lane base
        const int cbi = cb0 + i;

        const float a1 = s_sig[ca];
        float b1[6];
#pragma unroll
        for (int j = 0; j < 6; ++j) b1[j] = s_sig[cb0 + j];

        const float m1 = a1 + b1[i];

        // M2 row i (2x): M2[j] = A2[i][j] + B2[i][j] + 2 a1 b1[j]
        float A2r[6], M2[6];
#pragma unroll
        for (int j = 0; j < 6; ++j) {
            A2r[j] = s_sig[(1 + j) * SCOL + ca];
            M2[j]  = A2r[j] + s_sig[(1 + j) * SCOL + cbi] + 2.0f * a1 * b1[j];
        }

        r1 = m1 - dc[i];

        const float c2 = dc[i] - 2.0f * m1;
#pragma unroll
        for (int j = 0; j < 6; ++j) r2[j] = fmaf(c2, dc[j], M2[j]);

        const float t3a1 = 3.0f * a1;
        const float c3   = 3.0f * m1 - dc[i];
#pragma unroll
        for (int j = 0; j < 6; ++j) {
            const float a2b  = 3.0f * A2r[j];
            const float coef = fmaf(c3, dc[j], -3.0f * M2[j]);
#pragma unroll
            for (int k = 0; k < 6; ++k) {
                float v = s_sig[(7 + j * 6 + k) * SCOL + ca]
                        + s_sig[(7 + j * 6 + k) * SCOL + cbi];
                v = fmaf(a2b, b1[k], v);
                v = fmaf(t3a1, s_sig[(1 + k) * SCOL + cb0 + j], v);
                r3[j][k] = fmaf(coef, dc[k], v);
            }
        }
    }
    __syncthreads();   // all s_sig reads done before output staging overwrites

    // ---- stage output in smem as [wl][258] ----
    if (cw) {
        float* __restrict__ so = sm + mc * 258;
        so[i] = r1;
#pragma unroll
        for (int j = 0; j < 6; ++j) so[6 + i * 6 + j] = r2[j];
#pragma unroll
        for (int j = 0; j < 6; ++j)
#pragma unroll
            for (int k = 0; k < 6; ++k) so[42 + i * 36 + j * 6 + k] = r3[j][k];
    }
    __syncthreads();

    // ---- coalesced copy to global ----
    const int nwin = (g == 3) ? (NW - 3 * NWL) : NWL;    // 15 for g=3 else 16
    const int cnt  = nwin * 258;
    float* __restrict__ gout = out + ((long long)b * NW + NWL * g) * 258;
    for (int idx = tid; idx < cnt; idx += THREADS) gout[idx] = sm[idx];
}

}  // namespace

extern "C" void kernel_launch(void* const* d_in, const int* in_sizes, int n_in,
                              void* d_out, int out_size) {
    const float* path = (const float*)d_in[0];
    float* out = (float*)d_out;
    fused_kernel<<<BATCH * 4, THREADS>>>(path, out);
}

// round 10
// speedup vs baseline: 2.1346x; 1.0313x over previous
#include <cuda_runtime.h>

// Fused depth-3 sliding-window path signature (Chen chunk factorization),
// fine-grained: 7 blocks per batch x 64 threads (2 warps).
// B=256, L=2048, C=6, WIN=64, STRIDE=32 -> 63 windows / batch.
// Grid = 1792 blocks (batch = blk/7, group g = blk%7), 9 windows per block.
// Scan state: s1, T2 = 3*(2*s2), S3 = 6*s3. coef_j = a*d_j + T2[j] (1 FMA).
// dx staged as 3 float2 rows -> 3 LDS.64 + 1 LDS.32 per scan step.
// Output: combine -> regs -> smem [wl][258] -> coalesced block copy to global.

namespace {

constexpr int BATCH   = 256;
constexpr int LEN     = 2048;
constexpr int CH      = 6;
constexpr int NW      = 63;
constexpr int GROUPS  = 7;
constexpr int THREADS = 64;
constexpr int NCHUNKL = 10;               // chunks per block (1 overlap)
constexpr int NWL     = 9;                // windows per block (7*9 = 63 exact)
constexpr int NDXL    = 320;              // staged increments per block
constexpr int SROWD2  = 331;              // float2 row stride (320+10 pad, odd)
constexpr int NLANE   = NCHUNKL * CH;     // 60 scan lanes
constexpr int SCOL    = 61;               // sig column stride
constexpr int SM_FLOATS = 43 * SCOL;      // 2623 >= max(3*331*2=1986, 9*258=2322)

__global__ __launch_bounds__(THREADS, 14)
void fused_kernel(const float* __restrict__ path, float* __restrict__ out) {
    __shared__ __align__(16) float sm[SM_FLOATS];
    float2* __restrict__ s_dx2 = reinterpret_cast<float2*>(sm); // [3][SROWD2]
    float*  __restrict__ s_sig = sm;                            // [43][SCOL]

    const int tid = threadIdx.x;
    const int b   = blockIdx.x / GROUPS;
    const int g   = blockIdx.x - b * GROUPS;
    const int l0  = g * (NWL * 32);                 // 288 * g
    const float2* __restrict__ rowv =
        reinterpret_cast<const float2*>(path + (long long)b * (LEN * CH));
    // rowv[l*3 + pr] = channels (2pr, 2pr+1) at time l.

    // ---- stage increments as float2 (zero-fill global l >= 2047) ----
    for (int idx = tid; idx < NDXL * 3; idx += THREADS) {
        const int l  = idx / 3;
        const int pr = idx - l * 3;
        float2 d2 = make_float2(0.0f, 0.0f);
        const int gl = l0 + l;
        if (gl < LEN - 1) {
            const float2 v0 = rowv[gl * 3 + pr];
            const float2 v1 = rowv[gl * 3 + 3 + pr];
            d2.x = v1.x - v0.x;
            d2.y = v1.y - v0.y;
        }
        s_dx2[pr * SROWD2 + l + (l >> 5)] = d2;
    }
    __syncthreads();

    const int mc = tid / CH;       // local chunk 0..9 (tid>=60: idle lanes)
    const int i  = tid - mc * CH;  // leading channel
    const bool scan_lane = (tid < NLANE);

    float s1 = 0.0f;
    float T2[6];                   // 3 * S2  (S2 = 2*s2)
    float S3[6][6];                // 6 * s3
#pragma unroll
    for (int j = 0; j < 6; ++j) {
        T2[j] = 0.0f;
#pragma unroll
        for (int k = 0; k < 6; ++k) S3[j][k] = 0.0f;
    }

    if (scan_lane) {
        const int base = 33 * mc;  // padded float2 offset of local l = 32*mc
        const float* __restrict__ rowi = sm + 2 * (i >> 1) * SROWD2 + (i & 1);

#pragma unroll 4
        for (int t = 0; t < 32; ++t) {
            const int off = base + t;            // t<32: no extra pad term
            const float2 d01 = s_dx2[0 * SROWD2 + off];
            const float2 d23 = s_dx2[1 * SROWD2 + off];
            const float2 d45 = s_dx2[2 * SROWD2 + off];
            const float di = rowi[2 * off];

            const float a   = fmaf(3.0f, s1, di);          // di + 3 s1 (old s1)
            const float b23 = fmaf(6.0f, s1, 3.0f * di);   // 3*(di + 2 s1)

            const float d[6] = {d01.x, d01.y, d23.x, d23.y, d45.x, d45.y};

            float coef[6];                                  // uses old T2
#pragma unroll
            for (int j = 0; j < 6; ++j) coef[j] = fmaf(a, d[j], T2[j]);

#pragma unroll
            for (int j = 0; j < 6; ++j)
#pragma unroll
                for (int k = 0; k < 6; ++k)
                    S3[j][k] = fmaf(coef[j], d[k], S3[j][k]);

#pragma unroll
            for (int j = 0; j < 6; ++j) T2[j] = fmaf(b23, d[j], T2[j]);
            s1 += di;
        }
    }

    // ---- snapshot d_last for local window wl = mc (local l' = 32mc+63) ----
    float dc[6];
    {
        const int off = 33 * mc + 64;            // (32mc+63) + ((32mc+63)>>5)
        const bool cwn = (mc < NWL);
        float2 c01 = make_float2(0.0f, 0.0f), c23 = c01, c45 = c01;
        if (cwn) {
            c01 = s_dx2[0 * SROWD2 + off];
            c23 = s_dx2[1 * SROWD2 + off];
            c45 = s_dx2[2 * SROWD2 + off];
        }
        dc[0] = c01.x; dc[1] = c01.y; dc[2] = c23.x;
        dc[3] = c23.y; dc[4] = c45.x; dc[5] = c45.y;
    }
    __syncthreads();   // all dx reads done before s_sig overwrites

    // ---- publish chunk state: S2 = T2/3, column = tid ----
    if (scan_lane) {
        s_sig[tid] = s1;
        const float third = 1.0f / 3.0f;
#pragma unroll
        for (int j = 0; j < 6; ++j) s_sig[(1 + j) * SCOL + tid] = T2[j] * third;
#pragma unroll
        for (int j = 0; j < 6; ++j)
#pragma unroll
            for (int k = 0; k < 6; ++k)
                s_sig[(7 + j * 6 + k) * SCOL + tid] = S3[j][k];
    }
    __syncthreads();

    // ---- combine into registers: window w = 9g + mc ----
    const bool cw = (mc < NWL);    // w = 9g + mc <= 9*6+8 = 62 < NW always

    float r1 = 0.0f, r2[6], r3[6][6];
    if (cw) {
        const int ca  = tid;               // A_w lane i
        const int cb0 = (mc + 1) * CH;     // A_{w+1} lane base
        const int cbi = cb0 + i;

        const float a1 = s_sig[ca];
        float b1[6];
#pragma unroll
        for (int j = 0; j < 6; ++j) b1[j] = s_sig[cb0 + j];

        const float m1 = a1 + b1[i];

        // M2 row i (2x): M2[j] = A2[i][j] + B2[i][j] + 2 a1 b1[j]
        float A2r[6], M2[6];
#pragma unroll
        for (int j = 0; j < 6; ++j) {
            A2r[j] = s_sig[(1 + j) * SCOL + ca];
            M2[j]  = A2r[j] + s_sig[(1 + j) * SCOL + cbi] + 2.0f * a1 * b1[j];
        }

        r1 = m1 - dc[i];

        const float c2 = dc[i] - 2.0f * m1;
#pragma unroll
        for (int j = 0; j < 6; ++j) r2[j] = fmaf(c2, dc[j], M2[j]);

        const float t3a1 = 3.0f * a1;
        const float c3   = 3.0f * m1 - dc[i];
#pragma unroll
        for (int j = 0; j < 6; ++j) {
            const float a2b  = 3.0f * A2r[j];
            const float coef = fmaf(c3, dc[j], -3.0f * M2[j]);
#pragma unroll
            for (int k = 0; k < 6; ++k) {
                float v = s_sig[(7 + j * 6 + k) * SCOL + ca]
                        + s_sig[(7 + j * 6 + k) * SCOL + cbi];
                v = fmaf(a2b, b1[k], v);
                v = fmaf(t3a1, s_sig[(1 + k) * SCOL + cb0 + j], v);
                r3[j][k] = fmaf(coef, dc[k], v);
            }
        }
    }
    __syncthreads();   // all s_sig reads done before output staging overwrites

    // ---- stage output in smem as [wl][258] ----
    if (cw) {
        float* __restrict__ so = sm + mc * 258;
        so[i] = r1;
#pragma unroll
        for (int j = 0; j < 6; ++j) so[6 + i * 6 + j] = r2[j];
#pragma unroll
        for (int j = 0; j < 6; ++j)
#pragma unroll
            for (int k = 0; k < 6; ++k) so[42 + i * 36 + j * 6 + k] = r3[j][k];
    }
    __syncthreads();

    // ---- coalesced copy to global (all blocks identical: 9 windows) ----
    constexpr int CNT = NWL * 258;       // 2322
    float* __restrict__ gout = out + ((long long)b * NW + NWL * g) * 258;
    for (int idx = tid; idx < CNT; idx += THREADS) gout[idx] = sm[idx];
}

}  // namespace

extern "C" void kernel_launch(void* const* d_in, const int* in_sizes, int n_in,
                              void* d_out, int out_size) {
    const float* path = (const float*)d_in[0];
    float* out = (float*)d_out;
    fused_kernel<<<BATCH * GROUPS, THREADS>>>(path, out);
}